// round 13
// baseline (speedup 1.0000x reference)
#include <cuda_runtime.h>
#include <math.h>
#include <stdint.h>

#define BB  8
#define SS  4096
#define HH  768
#define NHH 12
#define LL  2
#define NSS 64
#define DHH 64
#define RR  (BB*NSS)   // 512 rows

// Scratch (device globals: no allocation allowed).
__device__ float g_buf[5][RR*HH];        // 0:x(tf32) 1:q 2:k 3:v 4:c(tf32)
__device__ float g_part[4][3][RR*HH];    // split-K partials [half][z]

__device__ __forceinline__ float to_tf32(float x){
    uint32_t u;
    asm("cvt.rna.tf32.f32 %0, %1;" : "=r"(u) : "f"(x));
    return __uint_as_float(u);
}
__device__ __forceinline__ float4 f4tf32(float4 a){
    return make_float4(to_tf32(a.x), to_tf32(a.y), to_tf32(a.z), to_tf32(a.w));
}
__device__ __forceinline__ void cp16(uint32_t sdst, const float* gsrc){
    asm volatile("cp.async.ca.shared.global [%0], [%1], 16;\n" :: "r"(sdst), "l"(gsrc));
}

// ---------------------------------------------------------------------------
// 1) Segment-mean pooling into g_buf[0] (token 0 excluded). Output tf32-
//    rounded (consumed only by the tf32 GEMM, which would round anyway).
// ---------------------------------------------------------------------------
__global__ void __launch_bounds__(192) pool_kernel(const int* __restrict__ sind,
                                                   const float* __restrict__ xin){
    const int n = blockIdx.x, b = blockIdx.y;
    __shared__ int lst[SS];
    __shared__ int cnt;
    const int tid = threadIdx.x;
    if (tid == 0) cnt = 0;
    __syncthreads();
    for (int s = tid; s < SS; s += 192){
        if (s > 0 && sind[b*SS + s] == n){
            int p = atomicAdd(&cnt, 1);
            lst[p] = s;
        }
    }
    __syncthreads();
    const int m = cnt;
    float4 acc = make_float4(0.f, 0.f, 0.f, 0.f);
    int t = 0;
    for (; t + 1 < m; t += 2){
        const float4 a = *((const float4*)(xin + ((size_t)(b*SS + lst[t  ]))*HH) + tid);
        const float4 c = *((const float4*)(xin + ((size_t)(b*SS + lst[t+1]))*HH) + tid);
        acc.x += a.x + c.x;
        acc.y += a.y + c.y;
        acc.z += a.z + c.z;
        acc.w += a.w + c.w;
    }
    if (t < m){
        const float4 a = *((const float4*)(xin + ((size_t)(b*SS + lst[t]))*HH) + tid);
        acc.x += a.x; acc.y += a.y; acc.z += a.z; acc.w += a.w;
    }
    const float inv = (m > 0) ? 1.f/(float)m : 0.f;
    float4 r = f4tf32(make_float4(acc.x*inv, acc.y*inv, acc.z*inv, acc.w*inv));
    *((float4*)(g_buf[0] + (size_t)(b*NSS + n)*HH) + tid) = r;
}

// ---------------------------------------------------------------------------
// 2) Split-K TF32 TC GEMM partial. 256 threads, 8 warps (2x4), warp tile
//    32x16. A already tf32 in gmem (no cvt); B cvt at fragment load.
// ---------------------------------------------------------------------------
#define PA 36
#define PB 72

#define LOAD_FRAGS(FA, FB, ST, KK)                                              \
    {                                                                           \
        _Pragma("unroll")                                                       \
        for (int mt = 0; mt < 2; mt++){                                         \
            int mb = wm*32 + mt*16;                                             \
            FA[mt][0] = __float_as_uint(As[ST][mb + g    ][(KK) + t4    ]);     \
            FA[mt][1] = __float_as_uint(As[ST][mb + g + 8][(KK) + t4    ]);     \
            FA[mt][2] = __float_as_uint(As[ST][mb + g    ][(KK) + t4 + 4]);     \
            FA[mt][3] = __float_as_uint(As[ST][mb + g + 8][(KK) + t4 + 4]);     \
        }                                                                       \
        _Pragma("unroll")                                                       \
        for (int nt = 0; nt < 2; nt++){                                         \
            int nb = wn*16 + nt*8;                                              \
            FB[nt][0] = __float_as_uint(to_tf32(Bs[ST][(KK) + t4    ][nb + g])); \
            FB[nt][1] = __float_as_uint(to_tf32(Bs[ST][(KK) + t4 + 4][nb + g])); \
        }                                                                       \
    }

#define DO_MMAS(FA, FB)                                                         \
    {                                                                           \
        _Pragma("unroll")                                                       \
        for (int mt = 0; mt < 2; mt++)                                          \
            _Pragma("unroll")                                                   \
            for (int nt = 0; nt < 2; nt++)                                      \
                asm volatile(                                                   \
                    "mma.sync.aligned.m16n8k8.row.col.f32.tf32.tf32.f32 "       \
                    "{%0,%1,%2,%3}, {%4,%5,%6,%7}, {%8,%9}, {%0,%1,%2,%3};"     \
                    : "+f"(acc[mt][nt][0]), "+f"(acc[mt][nt][1]),               \
                      "+f"(acc[mt][nt][2]), "+f"(acc[mt][nt][3])                \
                    : "r"(FA[mt][0]), "r"(FA[mt][1]), "r"(FA[mt][2]), "r"(FA[mt][3]), \
                      "r"(FB[nt][0]), "r"(FB[nt][1]));                          \
    }

__global__ void __launch_bounds__(256) gemm_part_kernel(int src, int nsplit,
                                                        const float* __restrict__ W0,
                                                        const float* __restrict__ W1,
                                                        const float* __restrict__ W2){
    const int z    = blockIdx.z / nsplit;
    const int half = blockIdx.z % nsplit;
    const float* __restrict__ A = g_buf[src];
    const float* __restrict__ W = (z == 0) ? W0 : (z == 1) ? W1 : W2;
    float* __restrict__ P = g_part[half][z];

    __shared__ float As[2][64][PA];
    __shared__ float Bs[2][32][PB];

    const int tid  = threadIdx.x;
    const int warp = tid >> 5, lane = tid & 31;
    const int wm = warp >> 2, wn = warp & 3;
    const int g  = lane >> 2, t4 = lane & 3;
    const int m0 = blockIdx.y * 64, n0 = blockIdx.x * 64;
    const int kbase = half * (HH / nsplit);
    const int T = (HH / 32) / nsplit;

    // cp.async: A 512 float4 chunks / 256 thr = 2 each; B likewise.
    uint32_t a_s[2], b_s[2];
    const float* a_g[2]; const float* b_g[2];
    #pragma unroll
    for (int i = 0; i < 2; i++){
        int ch = tid + i*256;
        int r = ch >> 3, c = ch & 7;
        a_s[i] = (uint32_t)__cvta_generic_to_shared(&As[0][r][c*4]);
        a_g[i] = A + (size_t)(m0 + r)*HH + kbase + c*4;
        int kr = ch >> 4, cb = ch & 15;
        b_s[i] = (uint32_t)__cvta_generic_to_shared(&Bs[0][kr][cb*4]);
        b_g[i] = W + (size_t)(kbase + kr)*HH + n0 + cb*4;
    }
    const uint32_t aStageB = (uint32_t)(64*PA*4);
    const uint32_t bStageB = (uint32_t)(32*PB*4);

    float acc[2][2][4];
    #pragma unroll
    for (int i = 0; i < 2; i++)
        #pragma unroll
        for (int j = 0; j < 2; j++)
            #pragma unroll
            for (int l = 0; l < 4; l++) acc[i][j][l] = 0.f;

    #pragma unroll
    for (int i = 0; i < 2; i++){
        cp16(a_s[i], a_g[i]);
        cp16(b_s[i], b_g[i]);
    }
    asm volatile("cp.async.commit_group;\n");

    uint32_t fa[2][2][4], fb[2][2][2];

    for (int t = 0; t < T; t++){
        const int cur = t & 1;
        if (t + 1 < T){
            const int nxt = cur ^ 1;
            const size_t koff = (size_t)(t+1)*32;
            #pragma unroll
            for (int i = 0; i < 2; i++){
                cp16(a_s[i] + nxt*aStageB, a_g[i] + koff);
                cp16(b_s[i] + nxt*bStageB, b_g[i] + koff*HH);
            }
            asm volatile("cp.async.commit_group;\n");
            asm volatile("cp.async.wait_group 1;\n");
        } else {
            asm volatile("cp.async.wait_group 0;\n");
        }
        __syncthreads();

        LOAD_FRAGS(fa[0], fb[0], cur, 0);
        #pragma unroll
        for (int ks = 0; ks < 4; ks++){
            const int pb = ks & 1;
            if (ks < 3){
                LOAD_FRAGS(fa[pb^1], fb[pb^1], cur, (ks+1)*8);
            }
            DO_MMAS(fa[pb], fb[pb]);
        }
        __syncthreads();
    }

    #pragma unroll
    for (int mt = 0; mt < 2; mt++){
        const int row = m0 + wm*32 + mt*16 + g;
        #pragma unroll
        for (int nt = 0; nt < 2; nt++){
            const int col = n0 + wn*16 + nt*8 + t4*2;
            P[(size_t)row*HH + col]         = acc[mt][nt][0];
            P[(size_t)row*HH + col + 1]     = acc[mt][nt][1];
            P[(size_t)(row+8)*HH + col]     = acc[mt][nt][2];
            P[(size_t)(row+8)*HH + col + 1] = acc[mt][nt][3];
        }
    }
}

// ---------------------------------------------------------------------------
// 2c) Wo reduce (4 parts) + bias + GELU + LayerNorm. One block per row.
//     Non-final output tf32-rounded (feeds next QKV GEMM); final output fp32.
// ---------------------------------------------------------------------------
__global__ void __launch_bounds__(192) reducewo_ln_kernel(const float* __restrict__ bo,
                                                          const float* __restrict__ gamma,
                                                          const float* __restrict__ beta,
                                                          float* __restrict__ final_out,
                                                          int is_final){
    const int row = blockIdx.x, tid = threadIdx.x;
    const int c = tid * 4;
    const size_t off = (size_t)row*HH + c;
    float4 p0 = *(const float4*)(g_part[0][0] + off);
    float4 p1 = *(const float4*)(g_part[1][0] + off);
    float4 p2 = *(const float4*)(g_part[2][0] + off);
    float4 p3 = *(const float4*)(g_part[3][0] + off);
    float4 bb = *(const float4*)(bo + c);
    float v[4];
    v[0] = p0.x + p1.x + p2.x + p3.x + bb.x;
    v[1] = p0.y + p1.y + p2.y + p3.y + bb.y;
    v[2] = p0.z + p1.z + p2.z + p3.z + bb.z;
    v[3] = p0.w + p1.w + p2.w + p3.w + bb.w;
    #pragma unroll
    for (int i = 0; i < 4; i++)
        v[i] = 0.5f*v[i]*(1.f + erff(v[i]*0.70710678118654752f));

    __shared__ float red[6];
    float s = v[0] + v[1] + v[2] + v[3];
    #pragma unroll
    for (int o = 16; o > 0; o >>= 1) s += __shfl_xor_sync(0xffffffffu, s, o);
    if ((tid & 31) == 0) red[tid >> 5] = s;
    __syncthreads();
    float tot = 0.f;
    #pragma unroll
    for (int i = 0; i < 6; i++) tot += red[i];
    const float mean = tot * (1.f/768.f);
    __syncthreads();

    float d[4];
    #pragma unroll
    for (int i = 0; i < 4; i++) d[i] = v[i] - mean;
    float qs = d[0]*d[0] + d[1]*d[1] + d[2]*d[2] + d[3]*d[3];
    #pragma unroll
    for (int o = 16; o > 0; o >>= 1) qs += __shfl_xor_sync(0xffffffffu, qs, o);
    if ((tid & 31) == 0) red[tid >> 5] = qs;
    __syncthreads();
    float tq = 0.f;
    #pragma unroll
    for (int i = 0; i < 6; i++) tq += red[i];
    const float inv = rsqrtf(tq * (1.f/768.f) + 1e-12f);

    float4 gg = *(const float4*)(gamma + c);
    float4 be = *(const float4*)(beta + c);
    float4 r;
    r.x = d[0]*inv*gg.x + be.x;
    r.y = d[1]*inv*gg.y + be.y;
    r.z = d[2]*inv*gg.z + be.z;
    r.w = d[3]*inv*gg.w + be.w;
    if (is_final){
        *(float4*)(final_out + off) = r;
    } else {
        *(float4*)(g_buf[0] + off) = f4tf32(r);
    }
}

// ---------------------------------------------------------------------------
// 3) Attention with fused QKV split-K reduce + bias. grid (NH, B, 4);
//    16 query rows/block, 2 rows/warp. ctx stored tf32-rounded (feeds Wo GEMM).
// ---------------------------------------------------------------------------
__device__ __forceinline__ float4 f4add3(float4 a, float4 b, float4 c){
    return make_float4(a.x+b.x+c.x, a.y+b.y+c.y, a.z+b.z+c.z, a.w+b.w+c.w);
}

__global__ void __launch_bounds__(256) attn_kernel(const float* __restrict__ bq,
                                                   const float* __restrict__ bk,
                                                   const float* __restrict__ bv){
    float* __restrict__ ctx = g_buf[4];
    const int h = blockIdx.x, b = blockIdx.y, q0 = blockIdx.z * 16;

    __shared__ float Ks[64][68];   // [j][d]
    __shared__ float Vt[64][68];   // [d][j] transposed
    __shared__ float Qs[16][68];   // [r][d]; per-warp 2-row slice reused for probs

    const int tid = threadIdx.x, warp = tid >> 5, lane = tid & 31;
    const size_t base = ((size_t)b*NSS)*HH + (size_t)h*DHH;

    // K, V: 64x64, fused reduce (2 parts) + bias.
    #pragma unroll
    for (int j = 0; j < 4; j++){
        int fidx = tid + j*256;
        int s = fidx >> 4, d4 = fidx & 15;
        const size_t off = base + (size_t)s*HH + d4*4;
        float4 kb = *(const float4*)(bk + h*DHH + d4*4);
        float4 vb = *(const float4*)(bv + h*DHH + d4*4);
        float4 kv = f4add3(*(const float4*)(g_part[0][1] + off),
                           *(const float4*)(g_part[1][1] + off), kb);
        float4 vv = f4add3(*(const float4*)(g_part[0][2] + off),
                           *(const float4*)(g_part[1][2] + off), vb);
        *(float4*)&Ks[s][d4*4] = kv;
        Vt[d4*4+0][s] = vv.x;
        Vt[d4*4+1][s] = vv.y;
        Vt[d4*4+2][s] = vv.z;
        Vt[d4*4+3][s] = vv.w;
    }
    // Q: 16 rows, fused reduce + bias. 256 positions exactly.
    {
        int r = tid >> 4, d4 = tid & 15;
        const size_t off = base + (size_t)(q0 + r)*HH + d4*4;
        float4 qb = *(const float4*)(bq + h*DHH + d4*4);
        *(float4*)&Qs[r][d4*4] =
            f4add3(*(const float4*)(g_part[0][0] + off),
                   *(const float4*)(g_part[1][0] + off), qb);
    }
    __syncthreads();

    const float4* Ks4 = (const float4*)&Ks[0][0];
    const float4* Vt4 = (const float4*)&Vt[0][0];
    const float4* Qs4 = (const float4*)&Qs[0][0];

    // ---- scores
    float s0[2], s1[2];
    #pragma unroll
    for (int ii = 0; ii < 2; ii++){ s0[ii] = 0.f; s1[ii] = 0.f; }
    #pragma unroll
    for (int d4 = 0; d4 < 16; d4++){
        float4 k0 = Ks4[lane*17 + d4];
        float4 k1 = Ks4[(lane+32)*17 + d4];
        #pragma unroll
        for (int ii = 0; ii < 2; ii++){
            float4 qv = Qs4[(warp*2 + ii)*17 + d4];   // broadcast
            s0[ii] = fmaf(qv.x, k0.x, fmaf(qv.y, k0.y, fmaf(qv.z, k0.z, fmaf(qv.w, k0.w, s0[ii]))));
            s1[ii] = fmaf(qv.x, k1.x, fmaf(qv.y, k1.y, fmaf(qv.z, k1.z, fmaf(qv.w, k1.w, s1[ii]))));
        }
    }

    // ---- softmax; probs into this warp's own Qs slice
    float* Psw = &Qs[warp*2][0];   // 136 floats available, use 128
    const float scale = 0.125f;
    #pragma unroll
    for (int ii = 0; ii < 2; ii++){
        float a = s0[ii]*scale, c = s1[ii]*scale;
        float m = fmaxf(a, c);
        #pragma unroll
        for (int o = 16; o > 0; o >>= 1) m = fmaxf(m, __shfl_xor_sync(0xffffffffu, m, o));
        float p0 = __expf(a - m), p1 = __expf(c - m);
        float sum = p0 + p1;
        #pragma unroll
        for (int o = 16; o > 0; o >>= 1) sum += __shfl_xor_sync(0xffffffffu, sum, o);
        const float inv = 1.f/sum;
        Psw[ii*64 + lane]      = p0*inv;
        Psw[ii*64 + lane + 32] = p1*inv;
    }
    __syncwarp();
    const float4* Psw4 = (const float4*)Psw;

    // ---- ctx
    float acc0[2], acc1[2];
    #pragma unroll
    for (int ii = 0; ii < 2; ii++){ acc0[ii] = 0.f; acc1[ii] = 0.f; }
    #pragma unroll
    for (int j4 = 0; j4 < 16; j4++){
        float4 v0 = Vt4[lane*17 + j4];
        float4 v1 = Vt4[(lane+32)*17 + j4];
        #pragma unroll
        for (int ii = 0; ii < 2; ii++){
            float4 pv = Psw4[ii*16 + j4];   // broadcast
            acc0[ii] = fmaf(pv.x, v0.x, fmaf(pv.y, v0.y, fmaf(pv.z, v0.z, fmaf(pv.w, v0.w, acc0[ii]))));
            acc1[ii] = fmaf(pv.x, v1.x, fmaf(pv.y, v1.y, fmaf(pv.z, v1.z, fmaf(pv.w, v1.w, acc1[ii]))));
        }
    }

    #pragma unroll
    for (int ii = 0; ii < 2; ii++){
        const int row = q0 + warp*2 + ii;
        ctx[base + (size_t)row*HH + lane]      = to_tf32(acc0[ii]);
        ctx[base + (size_t)row*HH + lane + 32] = to_tf32(acc1[ii]);
    }
}

// ---------------------------------------------------------------------------
extern "C" void kernel_launch(void* const* d_in, const int* in_sizes, int n_in,
                              void* d_out, int out_size){
    const int*   sind = (const int*)  d_in[0];
    const float* sl   = (const float*)d_in[1];
    const float* Wq   = (const float*)d_in[2];
    const float* bq   = (const float*)d_in[3];
    const float* Wk   = (const float*)d_in[4];
    const float* bk   = (const float*)d_in[5];
    const float* Wv   = (const float*)d_in[6];
    const float* bv   = (const float*)d_in[7];
    const float* Wo   = (const float*)d_in[8];
    const float* bo   = (const float*)d_in[9];
    const float* lg   = (const float*)d_in[10];
    const float* lb   = (const float*)d_in[11];
    float* out = (float*)d_out;

    pool_kernel<<<dim3(NSS, BB), 192>>>(sind, sl);

    for (int i = 0; i < LL; i++){
        const size_t wo = (size_t)i*HH*HH;
        // QKV: split-K=2 -> gridDim.z = 6; partials consumed by attn.
        gemm_part_kernel<<<dim3(HH/64, RR/64, 6), 256>>>(0, 2,
            Wq + wo, Wk + wo, Wv + wo);
        attn_kernel<<<dim3(NHH, BB, 4), 256>>>(bq + i*HH, bk + i*HH, bv + i*HH);
        // Wo: split-K=4 -> gridDim.z = 4
        gemm_part_kernel<<<dim3(HH/64, RR/64, 4), 256>>>(4, 4,
            Wo + wo, Wo + wo, Wo + wo);
        reducewo_ln_kernel<<<RR, 192>>>(bo + i*HH, lg + i*HH, lb + i*HH,
                                        out, (i == LL-1) ? 1 : 0);
    }
}

// round 14
// speedup vs baseline: 1.1208x; 1.1208x over previous
#include <cuda_runtime.h>
#include <math.h>
#include <stdint.h>

#define BB  8
#define SS  4096
#define HH  768
#define NHH 12
#define LL  2
#define NSS 64
#define DHH 64
#define RR  (BB*NSS)   // 512 rows

// Scratch (device globals: no allocation allowed).
__device__ float g_buf[5][RR*HH];        // 0:x(tf32) 1..3:unused 4:c(tf32)
__device__ float g_part[4][3][RR*HH];    // split-K partials [half][z]

__device__ __forceinline__ float to_tf32(float x){
    uint32_t u;
    asm("cvt.rna.tf32.f32 %0, %1;" : "=r"(u) : "f"(x));
    return __uint_as_float(u);
}
__device__ __forceinline__ float4 f4tf32(float4 a){
    return make_float4(to_tf32(a.x), to_tf32(a.y), to_tf32(a.z), to_tf32(a.w));
}
__device__ __forceinline__ void cp16(uint32_t sdst, const float* gsrc){
    asm volatile("cp.async.ca.shared.global [%0], [%1], 16;\n" :: "r"(sdst), "l"(gsrc));
}
// PDL primitives (no-ops when launch lacks the attribute)
__device__ __forceinline__ void gdc_wait(){
    asm volatile("griddepcontrol.wait;" ::: "memory");
}
__device__ __forceinline__ void gdc_launch(){
    asm volatile("griddepcontrol.launch_dependents;");
}

// ---------------------------------------------------------------------------
// 1) Segment-mean pooling into g_buf[0] (token 0 excluded). tf32-rounded out.
// ---------------------------------------------------------------------------
__global__ void __launch_bounds__(192) pool_kernel(const int* __restrict__ sind,
                                                   const float* __restrict__ xin){
    const int n = blockIdx.x, b = blockIdx.y;
    __shared__ int lst[SS];
    __shared__ int cnt;
    const int tid = threadIdx.x;
    if (tid == 0) cnt = 0;
    __syncthreads();
    for (int s = tid; s < SS; s += 192){
        if (s > 0 && sind[b*SS + s] == n){
            int p = atomicAdd(&cnt, 1);
            lst[p] = s;
        }
    }
    __syncthreads();
    const int m = cnt;
    float4 acc = make_float4(0.f, 0.f, 0.f, 0.f);
    int t = 0;
    for (; t + 1 < m; t += 2){
        const float4 a = *((const float4*)(xin + ((size_t)(b*SS + lst[t  ]))*HH) + tid);
        const float4 c = *((const float4*)(xin + ((size_t)(b*SS + lst[t+1]))*HH) + tid);
        acc.x += a.x + c.x;
        acc.y += a.y + c.y;
        acc.z += a.z + c.z;
        acc.w += a.w + c.w;
    }
    if (t < m){
        const float4 a = *((const float4*)(xin + ((size_t)(b*SS + lst[t]))*HH) + tid);
        acc.x += a.x; acc.y += a.y; acc.z += a.z; acc.w += a.w;
    }
    const float inv = (m > 0) ? 1.f/(float)m : 0.f;
    float4 r = f4tf32(make_float4(acc.x*inv, acc.y*inv, acc.z*inv, acc.w*inv));
    *((float4*)(g_buf[0] + (size_t)(b*NSS + n)*HH) + tid) = r;
    gdc_launch();
}

// ---------------------------------------------------------------------------
// 2) Split-K TF32 TC GEMM partial. 128 threads, 4 warps (2x2), warp tile
//    32x32 (R9 config — proven fastest). A pre-rounded tf32 (no cvt in loop);
//    B cvt at fragment load. PDL: W stage-0 loads issued before gdc_wait.
// ---------------------------------------------------------------------------
#define PA 36
#define PB 72

#define LOAD_FRAGS(FA, FB, ST, KK)                                              \
    {                                                                           \
        _Pragma("unroll")                                                       \
        for (int mt = 0; mt < 2; mt++){                                         \
            int mb = wm*32 + mt*16;                                             \
            FA[mt][0] = __float_as_uint(As[ST][mb + g    ][(KK) + t4    ]);     \
            FA[mt][1] = __float_as_uint(As[ST][mb + g + 8][(KK) + t4    ]);     \
            FA[mt][2] = __float_as_uint(As[ST][mb + g    ][(KK) + t4 + 4]);     \
            FA[mt][3] = __float_as_uint(As[ST][mb + g + 8][(KK) + t4 + 4]);     \
        }                                                                       \
        _Pragma("unroll")                                                       \
        for (int nt = 0; nt < 4; nt++){                                         \
            int nb = wn*32 + nt*8;                                              \
            FB[nt][0] = __float_as_uint(to_tf32(Bs[ST][(KK) + t4    ][nb + g])); \
            FB[nt][1] = __float_as_uint(to_tf32(Bs[ST][(KK) + t4 + 4][nb + g])); \
        }                                                                       \
    }

#define DO_MMAS(FA, FB)                                                         \
    {                                                                           \
        _Pragma("unroll")                                                       \
        for (int mt = 0; mt < 2; mt++)                                          \
            _Pragma("unroll")                                                   \
            for (int nt = 0; nt < 4; nt++)                                      \
                asm volatile(                                                   \
                    "mma.sync.aligned.m16n8k8.row.col.f32.tf32.tf32.f32 "       \
                    "{%0,%1,%2,%3}, {%4,%5,%6,%7}, {%8,%9}, {%0,%1,%2,%3};"     \
                    : "+f"(acc[mt][nt][0]), "+f"(acc[mt][nt][1]),               \
                      "+f"(acc[mt][nt][2]), "+f"(acc[mt][nt][3])                \
                    : "r"(FA[mt][0]), "r"(FA[mt][1]), "r"(FA[mt][2]), "r"(FA[mt][3]), \
                      "r"(FB[nt][0]), "r"(FB[nt][1]));                          \
    }

__global__ void __launch_bounds__(128) gemm_part_kernel(int src, int nsplit,
                                                        const float* __restrict__ W0,
                                                        const float* __restrict__ W1,
                                                        const float* __restrict__ W2){
    const int z    = blockIdx.z / nsplit;
    const int half = blockIdx.z % nsplit;
    const float* __restrict__ A = g_buf[src];
    const float* __restrict__ W = (z == 0) ? W0 : (z == 1) ? W1 : W2;
    float* __restrict__ P = g_part[half][z];

    __shared__ float As[2][64][PA];
    __shared__ float Bs[2][32][PB];

    const int tid  = threadIdx.x;
    const int warp = tid >> 5, lane = tid & 31;
    const int wm = warp >> 1, wn = warp & 1;
    const int g  = lane >> 2, t4 = lane & 3;
    const int m0 = blockIdx.y * 64, n0 = blockIdx.x * 64;
    const int kbase = half * (HH / nsplit);
    const int T = (HH / 32) / nsplit;

    uint32_t a_s[4], b_s[4];
    const float* a_g[4]; const float* b_g[4];
    #pragma unroll
    for (int i = 0; i < 4; i++){
        int ch = tid + i*128;
        int r = ch >> 3, c = ch & 7;
        a_s[i] = (uint32_t)__cvta_generic_to_shared(&As[0][r][c*4]);
        a_g[i] = A + (size_t)(m0 + r)*HH + kbase + c*4;
        int kr = ch >> 4, cb = ch & 15;
        b_s[i] = (uint32_t)__cvta_generic_to_shared(&Bs[0][kr][cb*4]);
        b_g[i] = W + (size_t)(kbase + kr)*HH + n0 + cb*4;
    }
    const uint32_t aStageB = (uint32_t)(64*PA*4);
    const uint32_t bStageB = (uint32_t)(32*PB*4);

    float acc[2][4][4];
    #pragma unroll
    for (int i = 0; i < 2; i++)
        #pragma unroll
        for (int j = 0; j < 4; j++)
            #pragma unroll
            for (int l = 0; l < 4; l++) acc[i][j][l] = 0.f;

    // W (independent of predecessor): start loading before the PDL wait.
    #pragma unroll
    for (int i = 0; i < 4; i++) cp16(b_s[i], b_g[i]);
    gdc_wait();
    #pragma unroll
    for (int i = 0; i < 4; i++) cp16(a_s[i], a_g[i]);
    asm volatile("cp.async.commit_group;\n");

    uint32_t fa[2][2][4], fb[2][4][2];

    for (int t = 0; t < T; t++){
        const int cur = t & 1;
        if (t + 1 < T){
            const int nxt = cur ^ 1;
            const size_t koff = (size_t)(t+1)*32;
            #pragma unroll
            for (int i = 0; i < 4; i++){
                cp16(a_s[i] + nxt*aStageB, a_g[i] + koff);
                cp16(b_s[i] + nxt*bStageB, b_g[i] + koff*HH);
            }
            asm volatile("cp.async.commit_group;\n");
            asm volatile("cp.async.wait_group 1;\n");
        } else {
            asm volatile("cp.async.wait_group 0;\n");
        }
        __syncthreads();

        LOAD_FRAGS(fa[0], fb[0], cur, 0);
        #pragma unroll
        for (int ks = 0; ks < 4; ks++){
            const int pb = ks & 1;
            if (ks < 3){
                LOAD_FRAGS(fa[pb^1], fb[pb^1], cur, (ks+1)*8);
            }
            DO_MMAS(fa[pb], fb[pb]);
        }
        __syncthreads();
    }

    #pragma unroll
    for (int mt = 0; mt < 2; mt++){
        const int row = m0 + wm*32 + mt*16 + g;
        #pragma unroll
        for (int nt = 0; nt < 4; nt++){
            const int col = n0 + wn*32 + nt*8 + t4*2;
            P[(size_t)row*HH + col]         = acc[mt][nt][0];
            P[(size_t)row*HH + col + 1]     = acc[mt][nt][1];
            P[(size_t)(row+8)*HH + col]     = acc[mt][nt][2];
            P[(size_t)(row+8)*HH + col + 1] = acc[mt][nt][3];
        }
    }
    gdc_launch();
}

// ---------------------------------------------------------------------------
// 2c) Wo reduce (4 parts) + bias + GELU + LayerNorm. One block per row.
// ---------------------------------------------------------------------------
__global__ void __launch_bounds__(192) reducewo_ln_kernel(const float* __restrict__ bo,
                                                          const float* __restrict__ gamma,
                                                          const float* __restrict__ beta,
                                                          float* __restrict__ final_out,
                                                          int is_final){
    const int row = blockIdx.x, tid = threadIdx.x;
    const int c = tid * 4;
    const size_t off = (size_t)row*HH + c;
    gdc_wait();
    float4 p0 = *(const float4*)(g_part[0][0] + off);
    float4 p1 = *(const float4*)(g_part[1][0] + off);
    float4 p2 = *(const float4*)(g_part[2][0] + off);
    float4 p3 = *(const float4*)(g_part[3][0] + off);
    float4 bb = *(const float4*)(bo + c);
    float v[4];
    v[0] = p0.x + p1.x + p2.x + p3.x + bb.x;
    v[1] = p0.y + p1.y + p2.y + p3.y + bb.y;
    v[2] = p0.z + p1.z + p2.z + p3.z + bb.z;
    v[3] = p0.w + p1.w + p2.w + p3.w + bb.w;
    #pragma unroll
    for (int i = 0; i < 4; i++)
        v[i] = 0.5f*v[i]*(1.f + erff(v[i]*0.70710678118654752f));

    __shared__ float red[6];
    float s = v[0] + v[1] + v[2] + v[3];
    #pragma unroll
    for (int o = 16; o > 0; o >>= 1) s += __shfl_xor_sync(0xffffffffu, s, o);
    if ((tid & 31) == 0) red[tid >> 5] = s;
    __syncthreads();
    float tot = 0.f;
    #pragma unroll
    for (int i = 0; i < 6; i++) tot += red[i];
    const float mean = tot * (1.f/768.f);
    __syncthreads();

    float d[4];
    #pragma unroll
    for (int i = 0; i < 4; i++) d[i] = v[i] - mean;
    float qs = d[0]*d[0] + d[1]*d[1] + d[2]*d[2] + d[3]*d[3];
    #pragma unroll
    for (int o = 16; o > 0; o >>= 1) qs += __shfl_xor_sync(0xffffffffu, qs, o);
    if ((tid & 31) == 0) red[tid >> 5] = qs;
    __syncthreads();
    float tq = 0.f;
    #pragma unroll
    for (int i = 0; i < 6; i++) tq += red[i];
    const float inv = rsqrtf(tq * (1.f/768.f) + 1e-12f);

    float4 gg = *(const float4*)(gamma + c);
    float4 be = *(const float4*)(beta + c);
    float4 r;
    r.x = d[0]*inv*gg.x + be.x;
    r.y = d[1]*inv*gg.y + be.y;
    r.z = d[2]*inv*gg.z + be.z;
    r.w = d[3]*inv*gg.w + be.w;
    if (is_final){
        *(float4*)(final_out + off) = r;
    } else {
        *(float4*)(g_buf[0] + off) = f4tf32(r);
    }
    gdc_launch();
}

// ---------------------------------------------------------------------------
// 3) Attention with fused QKV split-K reduce + bias. grid (NH, B, 4);
//    16 query rows/block, 2 rows/warp. ctx stored tf32-rounded.
// ---------------------------------------------------------------------------
__device__ __forceinline__ float4 f4add3(float4 a, float4 b, float4 c){
    return make_float4(a.x+b.x+c.x, a.y+b.y+c.y, a.z+b.z+c.z, a.w+b.w+c.w);
}

__global__ void __launch_bounds__(256) attn_kernel(const float* __restrict__ bq,
                                                   const float* __restrict__ bk,
                                                   const float* __restrict__ bv){
    float* __restrict__ ctx = g_buf[4];
    const int h = blockIdx.x, b = blockIdx.y, q0 = blockIdx.z * 16;

    __shared__ float Ks[64][68];   // [j][d]
    __shared__ float Vt[64][68];   // [d][j] transposed
    __shared__ float Qs[16][68];   // [r][d]; per-warp 2-row slice reused for probs

    const int tid = threadIdx.x, warp = tid >> 5, lane = tid & 31;
    const size_t base = ((size_t)b*NSS)*HH + (size_t)h*DHH;

    gdc_wait();
    // K, V: 64x64, fused reduce (2 parts) + bias.
    #pragma unroll
    for (int j = 0; j < 4; j++){
        int fidx = tid + j*256;
        int s = fidx >> 4, d4 = fidx & 15;
        const size_t off = base + (size_t)s*HH + d4*4;
        float4 kb = *(const float4*)(bk + h*DHH + d4*4);
        float4 vb = *(const float4*)(bv + h*DHH + d4*4);
        float4 kv = f4add3(*(const float4*)(g_part[0][1] + off),
                           *(const float4*)(g_part[1][1] + off), kb);
        float4 vv = f4add3(*(const float4*)(g_part[0][2] + off),
                           *(const float4*)(g_part[1][2] + off), vb);
        *(float4*)&Ks[s][d4*4] = kv;
        Vt[d4*4+0][s] = vv.x;
        Vt[d4*4+1][s] = vv.y;
        Vt[d4*4+2][s] = vv.z;
        Vt[d4*4+3][s] = vv.w;
    }
    // Q: 16 rows, fused reduce + bias.
    {
        int r = tid >> 4, d4 = tid & 15;
        const size_t off = base + (size_t)(q0 + r)*HH + d4*4;
        float4 qb = *(const float4*)(bq + h*DHH + d4*4);
        *(float4*)&Qs[r][d4*4] =
            f4add3(*(const float4*)(g_part[0][0] + off),
                   *(const float4*)(g_part[1][0] + off), qb);
    }
    __syncthreads();

    const float4* Ks4 = (const float4*)&Ks[0][0];
    const float4* Vt4 = (const float4*)&Vt[0][0];
    const float4* Qs4 = (const float4*)&Qs[0][0];

    float s0[2], s1[2];
    #pragma unroll
    for (int ii = 0; ii < 2; ii++){ s0[ii] = 0.f; s1[ii] = 0.f; }
    #pragma unroll
    for (int d4 = 0; d4 < 16; d4++){
        float4 k0 = Ks4[lane*17 + d4];
        float4 k1 = Ks4[(lane+32)*17 + d4];
        #pragma unroll
        for (int ii = 0; ii < 2; ii++){
            float4 qv = Qs4[(warp*2 + ii)*17 + d4];   // broadcast
            s0[ii] = fmaf(qv.x, k0.x, fmaf(qv.y, k0.y, fmaf(qv.z, k0.z, fmaf(qv.w, k0.w, s0[ii]))));
            s1[ii] = fmaf(qv.x, k1.x, fmaf(qv.y, k1.y, fmaf(qv.z, k1.z, fmaf(qv.w, k1.w, s1[ii]))));
        }
    }

    float* Psw = &Qs[warp*2][0];
    const float scale = 0.125f;
    #pragma unroll
    for (int ii = 0; ii < 2; ii++){
        float a = s0[ii]*scale, c = s1[ii]*scale;
        float m = fmaxf(a, c);
        #pragma unroll
        for (int o = 16; o > 0; o >>= 1) m = fmaxf(m, __shfl_xor_sync(0xffffffffu, m, o));
        float p0 = __expf(a - m), p1 = __expf(c - m);
        float sum = p0 + p1;
        #pragma unroll
        for (int o = 16; o > 0; o >>= 1) sum += __shfl_xor_sync(0xffffffffu, sum, o);
        const float inv = 1.f/sum;
        Psw[ii*64 + lane]      = p0*inv;
        Psw[ii*64 + lane + 32] = p1*inv;
    }
    __syncwarp();
    const float4* Psw4 = (const float4*)Psw;

    float acc0[2], acc1[2];
    #pragma unroll
    for (int ii = 0; ii < 2; ii++){ acc0[ii] = 0.f; acc1[ii] = 0.f; }
    #pragma unroll
    for (int j4 = 0; j4 < 16; j4++){
        float4 v0 = Vt4[lane*17 + j4];
        float4 v1 = Vt4[(lane+32)*17 + j4];
        #pragma unroll
        for (int ii = 0; ii < 2; ii++){
            float4 pv = Psw4[ii*16 + j4];   // broadcast
            acc0[ii] = fmaf(pv.x, v0.x, fmaf(pv.y, v0.y, fmaf(pv.z, v0.z, fmaf(pv.w, v0.w, acc0[ii]))));
            acc1[ii] = fmaf(pv.x, v1.x, fmaf(pv.y, v1.y, fmaf(pv.z, v1.z, fmaf(pv.w, v1.w, acc1[ii]))));
        }
    }

    #pragma unroll
    for (int ii = 0; ii < 2; ii++){
        const int row = q0 + warp*2 + ii;
        ctx[base + (size_t)row*HH + lane]      = to_tf32(acc0[ii]);
        ctx[base + (size_t)row*HH + lane + 32] = to_tf32(acc1[ii]);
    }
    gdc_launch();
}

// ---------------------------------------------------------------------------
// PDL launch helper: same default stream as <<<>>>, plus the programmatic
// stream-serialization attribute so griddepcontrol takes effect.
// ---------------------------------------------------------------------------
template<typename... Args>
static void pdl_launch(dim3 grid, dim3 block, void(*kern)(Args...), Args... args){
    cudaLaunchAttribute at[1];
    at[0].id = cudaLaunchAttributeProgrammaticStreamSerialization;
    at[0].val.programmaticStreamSerializationAllowed = 1;
    cudaLaunchConfig_t cfg;
    cfg.gridDim = grid;
    cfg.blockDim = block;
    cfg.dynamicSmemBytes = 0;
    cfg.stream = 0;
    cfg.attrs = at;
    cfg.numAttrs = 1;
    cudaLaunchKernelEx(&cfg, kern, args...);
}

// ---------------------------------------------------------------------------
extern "C" void kernel_launch(void* const* d_in, const int* in_sizes, int n_in,
                              void* d_out, int out_size){
    const int*   sind = (const int*)  d_in[0];
    const float* sl   = (const float*)d_in[1];
    const float* Wq   = (const float*)d_in[2];
    const float* bq   = (const float*)d_in[3];
    const float* Wk   = (const float*)d_in[4];
    const float* bk   = (const float*)d_in[5];
    const float* Wv   = (const float*)d_in[6];
    const float* bv   = (const float*)d_in[7];
    const float* Wo   = (const float*)d_in[8];
    const float* bo   = (const float*)d_in[9];
    const float* lg   = (const float*)d_in[10];
    const float* lb   = (const float*)d_in[11];
    float* out = (float*)d_out;

    pdl_launch(dim3(NSS, BB), dim3(192), pool_kernel, sind, sl);

    for (int i = 0; i < LL; i++){
        const size_t wo = (size_t)i*HH*HH;
        pdl_launch(dim3(HH/64, RR/64, 6), dim3(128), gemm_part_kernel,
                   0, 2, (const float*)(Wq + wo), (const float*)(Wk + wo),
                   (const float*)(Wv + wo));
        pdl_launch(dim3(NHH, BB, 4), dim3(256), attn_kernel,
                   (const float*)(bq + i*HH), (const float*)(bk + i*HH),
                   (const float*)(bv + i*HH));
        pdl_launch(dim3(HH/64, RR/64, 4), dim3(128), gemm_part_kernel,
                   4, 4, (const float*)(Wo + wo), (const float*)(Wo + wo),
                   (const float*)(Wo + wo));
        pdl_launch(dim3(RR), dim3(192), reducewo_ln_kernel,
                   (const float*)(bo + i*HH), (const float*)(lg + i*HH),
                   (const float*)(lb + i*HH), out, (i == LL-1) ? 1 : 0);
    }
}